// round 13
// baseline (speedup 1.0000x reference)
#include <cuda_runtime.h>
#include <math.h>

#define NB    8
#define NC    64
#define NPIX  1600
#define TOPK  10
#define TKPAD 12
#define NNZ   (NPIX * TOPK)
#define SORTN 2048
#define FULLW 0xFFFFFFFFu

// ---------------- static scratch (no runtime allocation) ----------------
__device__ float g_xx  [NB * NPIX];
__device__ unsigned long long g_skey[NB * NPIX];   // sorted (val,idx) keys
__device__ unsigned short g_rs[NB * NPIX];         // run start per sorted pos
__device__ unsigned short g_re[NB * NPIX];         // run end per sorted pos
__device__ int   g_dvc [NB * NPIX];                // DV counters (global)
__device__ int   g_topk[NB * NPIX * TKPAD];
__device__ float g_dv2 [NB * NPIX];
__device__ int   g_off [NB * (NPIX + 1)];
__device__ int   g_ecol[NB * NNZ];
__device__ float g_Z   [NB * NPIX * NC];
__device__ float g_Y   [NB * NPIX * NC];
__device__ float g_Hf  [NB * NPIX * NC];

__device__ __forceinline__ float4 f4add(float4 a, float4 b) {
    a.x += b.x; a.y += b.y; a.z += b.z; a.w += b.w; return a;
}
__device__ __forceinline__ unsigned long long u64min_(unsigned long long a, unsigned long long b) { return a < b ? a : b; }
__device__ __forceinline__ unsigned long long u64max_(unsigned long long a, unsigned long long b) { return a > b ? a : b; }

// ---------------- K1: fused [layer-1 GEMM tiles | 1x1 conv + counter init]
// blocks 0..199: gemm tile (b = blk/25, r0 = (blk%25)*64), Z = X@W1 + b1 (NO dv2 yet)
// blocks 200..255: conv for batch (idx/7), pixels ((idx%7)*256+t); zero g_dvc, out
__global__ void k_convgemm(const float* __restrict__ x,
                           const float* __restrict__ wc1,
                           const float* __restrict__ bc1,
                           const float* __restrict__ W,
                           const float* __restrict__ bias,
                           float* __restrict__ out)
{
    __shared__ float As[64 * 64];
    __shared__ float Ws[64 * 64];
    int t = threadIdx.x;

    if (blockIdx.x < 200) {
        int b  = blockIdx.x / 25;
        int r0 = (blockIdx.x - b * 25) * 64;
        const float* Xb = x + ((size_t)b * NPIX + r0) * NC;
        for (int i = t; i < 4096; i += 256) { As[i] = Xb[i]; Ws[i] = W[i]; }
        __syncthreads();
        int tx = t & 15, ty = t >> 4;
        int c4 = tx * 4, r4 = ty * 4;
        float acc[4][4];
        #pragma unroll
        for (int i = 0; i < 4; i++)
            #pragma unroll
            for (int j = 0; j < 4; j++) acc[i][j] = 0.f;
        for (int k = 0; k < 64; k += 4) {
            float4 w0 = *(const float4*)&Ws[(k+0)*64 + c4];
            float4 w1 = *(const float4*)&Ws[(k+1)*64 + c4];
            float4 w2 = *(const float4*)&Ws[(k+2)*64 + c4];
            float4 w3 = *(const float4*)&Ws[(k+3)*64 + c4];
            #pragma unroll
            for (int i = 0; i < 4; i++) {
                float4 a = *(const float4*)&As[(r4+i)*64 + k];
                acc[i][0] += a.x*w0.x + a.y*w1.x + a.z*w2.x + a.w*w3.x;
                acc[i][1] += a.x*w0.y + a.y*w1.y + a.z*w2.y + a.w*w3.y;
                acc[i][2] += a.x*w0.z + a.y*w1.z + a.z*w2.z + a.w*w3.z;
                acc[i][3] += a.x*w0.w + a.y*w1.w + a.z*w2.w + a.w*w3.w;
            }
        }
        float4 bv = *(const float4*)&bias[c4];
        #pragma unroll
        for (int i = 0; i < 4; i++) {
            int r = r0 + r4 + i;
            float4 o;
            o.x = acc[i][0] + bv.x;
            o.y = acc[i][1] + bv.y;
            o.z = acc[i][2] + bv.z;
            o.w = acc[i][3] + bv.w;
            *(float4*)&g_Z[((size_t)b*NPIX + r) * NC + c4] = o;   // raw; dv2 applied later
        }
    } else {
        int idx = blockIdx.x - 200;                 // 0..55
        int b = idx / 7;
        float* ws = As;                             // reuse smem
        if (t < NC) ws[t] = wc1[t];
        __syncthreads();
        int gid = idx * 256 + t;
        if (gid < NB * NPIX) g_dvc[gid] = 0;
        if (gid < NB) out[gid] = 0.f;
        int p = (idx - b * 7) * 256 + t;
        if (p >= NPIX) return;
        const float* xb = x + (size_t)b * NC * NPIX;
        float acc = bc1[0];
        #pragma unroll
        for (int c = 0; c < NC; c++) acc += xb[c*NPIX + p] * ws[c];
        g_xx[b*NPIX + p] = fmaxf(acc, 0.f);
    }
}

// ---------------- K2: softmax + sort + run bounds (8 blocks)
__global__ __launch_bounds__(1024) void k_sortA()
{
    int b = blockIdx.x, t = threadIdx.x;
    __shared__ unsigned long long skey[SORTN];      // 16 KB
    __shared__ float rf[1024];

    float v0 = g_xx[b*NPIX + t];
    float v1 = (t + 1024 < NPIX) ? g_xx[b*NPIX + t + 1024] : -3.4e38f;
    rf[t] = fmaxf(v0, v1); __syncthreads();
    for (int s = 512; s > 0; s >>= 1) { if (t < s) rf[t] = fmaxf(rf[t], rf[t+s]); __syncthreads(); }
    float mx = rf[0]; __syncthreads();
    float e0 = expf(v0 - mx);
    float e1 = (t + 1024 < NPIX) ? expf(v1 - mx) : 0.f;
    rf[t] = e0 + e1; __syncthreads();
    for (int s = 512; s > 0; s >>= 1) { if (t < s) rf[t] += rf[t+s]; __syncthreads(); }
    float inv = 1.f / rf[0]; __syncthreads();

    unsigned long long a0 = ((unsigned long long)__float_as_uint(e0 * inv) << 32) | (unsigned)t;
    unsigned long long a1 = (t + 1024 < NPIX)
        ? (((unsigned long long)__float_as_uint(e1 * inv) << 32) | (unsigned)(t + 1024))
        : 0xFFFFFFFFFFFFFFFFull;

    #define REGPHASE(KSZ, J) { \
        unsigned long long p0 = __shfl_xor_sync(FULLW, a0, (J)); \
        unsigned long long p1 = __shfl_xor_sync(FULLW, a1, (J)); \
        int i0 = t, i1 = t + 1024; \
        bool m0 = (((i0 & (J)) == 0) == ((i0 & (KSZ)) == 0)); \
        bool m1 = (((i1 & (J)) == 0) == ((i1 & (KSZ)) == 0)); \
        a0 = m0 ? u64min_(a0, p0) : u64max_(a0, p0); \
        a1 = m1 ? u64min_(a1, p1) : u64max_(a1, p1); }

    for (int ksz = 2; ksz <= 32; ksz <<= 1)
        for (int j = ksz >> 1; j >= 1; j >>= 1)
            REGPHASE(ksz, j);
    skey[t] = a0; skey[t + 1024] = a1; __syncthreads();

    for (int ksz = 64; ksz <= SORTN; ksz <<= 1) {
        int jstart = ksz >> 1;
        if (ksz == SORTN) {
            unsigned long long lo = u64min_(a0, a1), hi = u64max_(a0, a1);
            a0 = lo; a1 = hi;
            skey[t] = a0; skey[t + 1024] = a1; __syncthreads();
            jstart = 512;
        }
        for (int j = jstart; j >= 32; j >>= 1) {
            #pragma unroll
            for (int r = 0; r < 2; r++) {
                int i = t + r * 1024;
                int ixj = i ^ j;
                if (ixj > i) {
                    unsigned long long a = skey[i], c = skey[ixj];
                    bool up = ((i & ksz) == 0);
                    if ((a > c) == up) { skey[i] = c; skey[ixj] = a; }
                }
            }
            __syncthreads();
        }
        a0 = skey[t]; a1 = skey[t + 1024];
        for (int j = 16; j >= 1; j >>= 1)
            REGPHASE(ksz, j);
        skey[t] = a0; skey[t + 1024] = a1; __syncthreads();
    }

    for (int p = t; p < NPIX; p += 1024) {
        unsigned v = (unsigned)(skey[p] >> 32);
        int lo = 0, hi = p;
        while (lo < hi) { int m = (lo + hi) >> 1;
            if ((unsigned)(skey[m] >> 32) < v) lo = m + 1; else hi = m; }
        int lo2 = p + 1, hi2 = NPIX;
        while (lo2 < hi2) { int m = (lo2 + hi2) >> 1;
            if ((unsigned)(skey[m] >> 32) <= v) lo2 = m + 1; else hi2 = m; }
        g_skey[b*NPIX + p] = skey[p];
        g_rs[b*NPIX + p] = (unsigned short)lo;
        g_re[b*NPIX + p] = (unsigned short)(lo2 - 1);
    }
}

// ---------------- K3: top-k walk, 8 slices per batch (64 blocks)
__global__ __launch_bounds__(256) void k_walk()
{
    int b = blockIdx.y, slice = blockIdx.x, t = threadIdx.x;
    __shared__ unsigned long long sk[NPIX];
    __shared__ unsigned short rs[NPIX], re[NPIX];
    for (int p = t; p < NPIX; p += 256) {
        sk[p] = g_skey[b*NPIX + p];
        rs[p] = g_rs[b*NPIX + p];
        re[p] = g_re[b*NPIX + p];
    }
    __syncthreads();
    if (t >= 200) return;
    int p = slice * 200 + t;
    int i = (int)(sk[p] & 0xFFFFFFFFu);
    float vi = __uint_as_float((unsigned)(sk[p] >> 32));

    int out[TOPK]; int cnt = 0;
    int a = rs[p], bnd = re[p];
    for (int q = a; q <= bnd && cnt < TOPK; q++)
        out[cnt++] = (int)(sk[q] & 0xFFFFFFFFu);
    int L = a - 1, R = bnd + 1;
    while (cnt < TOPK) {
        float dL = (L >= 0)   ? vi - __uint_as_float((unsigned)(sk[L] >> 32)) : 3.4e38f;
        float dR = (R < NPIX) ? __uint_as_float((unsigned)(sk[R] >> 32)) - vi : 3.4e38f;
        if (dL < dR) {
            int s2 = rs[L];
            for (int q = s2; q <= L && cnt < TOPK; q++)
                out[cnt++] = (int)(sk[q] & 0xFFFFFFFFu);
            L = s2 - 1;
        } else if (dR < dL) {
            int e2 = re[R];
            for (int q = R; q <= e2 && cnt < TOPK; q++)
                out[cnt++] = (int)(sk[q] & 0xFFFFFFFFu);
            R = e2 + 1;
        } else {
            int sL = rs[L], eR = re[R];
            int qa = sL, qb = R;
            while (cnt < TOPK && (qa <= L || qb <= eR)) {
                int ia = (qa <= L)  ? (int)(sk[qa] & 0xFFFFFFFFu) : 0x7FFFFFFF;
                int ib = (qb <= eR) ? (int)(sk[qb] & 0xFFFFFFFFu) : 0x7FFFFFFF;
                if (ia < ib) { out[cnt++] = ia; qa++; }
                else         { out[cnt++] = ib; qb++; }
            }
            L = sL - 1; R = eR + 1;
        }
    }
    bool has = false;
    #pragma unroll
    for (int j2 = 0; j2 < TOPK; j2++) has |= (out[j2] == i);
    if (!has) out[TOPK-1] = i;

    int base = (b*NPIX + i) * TKPAD;
    #pragma unroll
    for (int j2 = 0; j2 < TOPK; j2++) {
        g_topk[base + j2] = out[j2];
        atomicAdd(&g_dvc[b*NPIX + out[j2]], 1);
    }
}

// ---------------- K4: scan -> offsets/dv2; CSR fill; scale Z by 0.1*dv2 (8 blocks)
__global__ __launch_bounds__(1024) void k_scanfill()
{
    int b = blockIdx.x, t = threadIdx.x;
    int lane = t & 31, wid = t >> 5;
    __shared__ int   off_s[NPIX + 1];
    __shared__ float dv2_s[NPIX];
    __shared__ int   cur_s[NPIX];
    __shared__ int   part[32];

    // phase A: scan
    int p0 = t * 2;
    int d0 = (p0 < NPIX) ? g_dvc[b*NPIX + p0] : 0;
    int d1 = (p0 + 1 < NPIX) ? g_dvc[b*NPIX + p0 + 1] : 0;
    int sv = d0 + d1;
    int incl = sv;
    #pragma unroll
    for (int d2 = 1; d2 < 32; d2 <<= 1) {
        int vv = __shfl_up_sync(FULLW, incl, d2);
        if (lane >= d2) incl += vv;
    }
    if (lane == 31) part[wid] = incl;
    __syncthreads();
    if (wid == 0) {
        int w = part[lane];
        #pragma unroll
        for (int d2 = 1; d2 < 32; d2 <<= 1) {
            int vv = __shfl_up_sync(FULLW, w, d2);
            if (lane >= d2) w += vv;
        }
        part[lane] = w;
    }
    __syncthreads();
    int total_incl = incl + (wid ? part[wid-1] : 0);
    if (p0 < NPIX) {
        int excl = total_incl - sv;
        off_s[p0] = excl; off_s[p0+1] = excl + d0;
        g_off[b*(NPIX+1) + p0]     = excl;
        g_off[b*(NPIX+1) + p0 + 1] = excl + d0;
        float f0 = rsqrtf((float)d0), f1 = rsqrtf((float)d1);
        dv2_s[p0] = f0; dv2_s[p0+1] = f1;
        g_dv2[b*NPIX + p0]     = f0;
        g_dv2[b*NPIX + p0 + 1] = f1;
        cur_s[p0] = 0; cur_s[p0+1] = 0;
    }
    if (t == 0) { off_s[NPIX] = NNZ; g_off[b*(NPIX+1) + NPIX] = NNZ; }
    __syncthreads();

    // phase B: CSR fill with smem cursors
    for (int s2 = t; s2 < NNZ; s2 += 1024) {
        int e = s2 / TOPK, j2 = s2 - e * TOPK;
        int v = g_topk[(b*NPIX + e) * TKPAD + j2];
        int ppos = atomicAdd(&cur_s[v], 1);
        g_ecol[b*NNZ + off_s[v] + ppos] = e;
    }

    // phase C: scale Z rows by 0.1*dv2 (independent of B)
    for (int i4 = t; i4 < NPIX * 16; i4 += 1024) {
        int v = i4 >> 4;
        float s = 0.1f * dv2_s[v];
        float4* zp = (float4*)&g_Z[((size_t)b*NPIX + v) * NC + (i4 & 15) * 4];
        float4 z = *zp;
        z.x *= s; z.y *= s; z.z *= s; z.w *= s;
        *zp = z;
    }
}

// ---------------- layer-2 GEMM: Z = 0.1*dv2 * (Hf@W + b)
__global__ void k_gemm2(const float* __restrict__ W,
                        const float* __restrict__ bias)
{
    int b  = blockIdx.y;
    int r0 = blockIdx.x * 64;
    __shared__ float As[64 * 64];
    __shared__ float Ws[64 * 64];
    int t = threadIdx.x;
    const float* Xb = g_Hf + ((size_t)b * NPIX + r0) * NC;
    for (int i = t; i < 4096; i += 256) { As[i] = Xb[i]; Ws[i] = W[i]; }
    __syncthreads();

    int tx = t & 15, ty = t >> 4;
    int c4 = tx * 4, r4 = ty * 4;
    float acc[4][4];
    #pragma unroll
    for (int i = 0; i < 4; i++)
        #pragma unroll
        for (int j = 0; j < 4; j++) acc[i][j] = 0.f;

    for (int k = 0; k < 64; k += 4) {
        float4 w0 = *(const float4*)&Ws[(k+0)*64 + c4];
        float4 w1 = *(const float4*)&Ws[(k+1)*64 + c4];
        float4 w2 = *(const float4*)&Ws[(k+2)*64 + c4];
        float4 w3 = *(const float4*)&Ws[(k+3)*64 + c4];
        #pragma unroll
        for (int i = 0; i < 4; i++) {
            float4 a = *(const float4*)&As[(r4+i)*64 + k];
            acc[i][0] += a.x*w0.x + a.y*w1.x + a.z*w2.x + a.w*w3.x;
            acc[i][1] += a.x*w0.y + a.y*w1.y + a.z*w2.y + a.w*w3.y;
            acc[i][2] += a.x*w0.z + a.y*w1.z + a.z*w2.z + a.w*w3.z;
            acc[i][3] += a.x*w0.w + a.y*w1.w + a.z*w2.w + a.w*w3.w;
        }
    }
    float4 bv = *(const float4*)&bias[c4];
    #pragma unroll
    for (int i = 0; i < 4; i++) {
        int r = r0 + r4 + i;
        float s = 0.1f * g_dv2[b*NPIX + r];
        float4 o;
        o.x = (acc[i][0] + bv.x) * s;
        o.y = (acc[i][1] + bv.y) * s;
        o.z = (acc[i][2] + bv.z) * s;
        o.w = (acc[i][3] + bv.w) * s;
        *(float4*)&g_Z[((size_t)b*NPIX + r) * NC + c4] = o;
    }
}

// ---------------- hyperedge gather
__global__ void k_edge()
{
    int b = blockIdx.y, t = threadIdx.x;
    int e  = blockIdx.x * 16 + (t >> 4);
    int c4 = (t & 15) * 4;
    const int* __restrict__ tk = &g_topk[(b*NPIX + e) * TKPAD];
    int4 i0 = *(const int4*)tk;
    int4 i1 = *(const int4*)(tk + 4);
    int2 i2 = *(const int2*)(tk + 8);
    float4 acc;
    acc =            *(const float4*)&g_Z[((b*NPIX + i0.x) << 6) + c4];
    acc = f4add(acc, *(const float4*)&g_Z[((b*NPIX + i0.y) << 6) + c4]);
    acc = f4add(acc, *(const float4*)&g_Z[((b*NPIX + i0.z) << 6) + c4]);
    acc = f4add(acc, *(const float4*)&g_Z[((b*NPIX + i0.w) << 6) + c4]);
    acc = f4add(acc, *(const float4*)&g_Z[((b*NPIX + i1.x) << 6) + c4]);
    acc = f4add(acc, *(const float4*)&g_Z[((b*NPIX + i1.y) << 6) + c4]);
    acc = f4add(acc, *(const float4*)&g_Z[((b*NPIX + i1.z) << 6) + c4]);
    acc = f4add(acc, *(const float4*)&g_Z[((b*NPIX + i1.w) << 6) + c4]);
    acc = f4add(acc, *(const float4*)&g_Z[((b*NPIX + i2.x) << 6) + c4]);
    acc = f4add(acc, *(const float4*)&g_Z[((b*NPIX + i2.y) << 6) + c4]);
    *(float4*)&g_Y[((b*NPIX + e) << 6) + c4] = acc;
}

// ---------------- vertex gather: block per vertex, 16 slices float4
__global__ void k_vertex()
{
    int b = blockIdx.y, u = blockIdx.x, t = threadIdx.x;
    int c4 = (t & 15) * 4, s = t >> 4;
    __shared__ float4 red[256];
    int o0 = g_off[b*(NPIX+1) + u];
    int o1 = g_off[b*(NPIX+1) + u + 1];
    float4 acc = make_float4(0.f, 0.f, 0.f, 0.f);
    for (int p = o0 + s; p < o1; p += 16) {
        int e = g_ecol[b*NNZ + p];
        acc = f4add(acc, *(const float4*)&g_Y[((b*NPIX + e) << 6) + c4]);
    }
    red[t] = acc; __syncthreads();
    if (t < 128) red[t] = f4add(red[t], red[t+128]); __syncthreads();
    if (t < 64)  red[t] = f4add(red[t], red[t+64]);  __syncthreads();
    if (t < 32)  red[t] = f4add(red[t], red[t+32]);  __syncthreads();
    if (t < 16) {
        float4 tot = f4add(red[t], red[t+16]);
        float sc = g_dv2[b*NPIX + u];
        float4 o;
        o.x = fmaxf(tot.x * sc, 0.f);
        o.y = fmaxf(tot.y * sc, 0.f);
        o.z = fmaxf(tot.z * sc, 0.f);
        o.w = fmaxf(tot.w * sc, 0.f);
        *(float4*)&g_Hf[((b*NPIX + u) << 6) + t*4] = o;
    }
}

// ---------------- final 1x1 conv + relu + per-batch sum
__global__ void k_final(const float* __restrict__ wc,
                        const float* __restrict__ bc,
                        float* __restrict__ out)
{
    int b = blockIdx.y, t = threadIdx.x;
    __shared__ float ws[NC];
    __shared__ float red[256];
    if (t < NC) ws[t] = wc[t];
    __syncthreads();
    const float* hb = g_Hf + (size_t)b * NPIX * NC;
    int p = blockIdx.x * 256 + t;
    float lsum = 0.f;
    if (p < NPIX) {
        float acc = bc[0];
        #pragma unroll
        for (int c = 0; c < NC; c++) acc += hb[c*NPIX + p] * ws[c];
        lsum = fmaxf(acc, 0.f);
    }
    red[t] = lsum; __syncthreads();
    for (int s = 128; s > 0; s >>= 1) { if (t < s) red[t] += red[t+s]; __syncthreads(); }
    if (t == 0) atomicAdd(&out[b], red[0]);
}

// ---------------- launch ----------------
extern "C" void kernel_launch(void* const* d_in, const int* in_sizes, int n_in,
                              void* d_out, int out_size)
{
    const float* x      = (const float*)d_in[0];
    const float* w_con1 = (const float*)d_in[1];
    const float* b_con1 = (const float*)d_in[2];
    const float* W1     = (const float*)d_in[3];
    const float* b1     = (const float*)d_in[4];
    const float* W2     = (const float*)d_in[5];
    const float* b2     = (const float*)d_in[6];
    const float* w_con2 = (const float*)d_in[7];
    const float* b_con2 = (const float*)d_in[8];
    float* out = (float*)d_out;

    k_convgemm<<<256, 256>>>(x, w_con1, b_con1, W1, b1, out);
    k_sortA<<<NB, 1024>>>();
    k_walk<<<dim3(8, NB), 256>>>();
    k_scanfill<<<NB, 1024>>>();

    // layer 1 (Z already scaled in k_scanfill)
    k_edge<<<dim3(NPIX / 16, NB), 256>>>();
    k_vertex<<<dim3(NPIX, NB), 256>>>();

    // layer 2
    k_gemm2<<<dim3(NPIX / 64, NB), 256>>>(W2, b2);
    k_edge<<<dim3(NPIX / 16, NB), 256>>>();
    k_vertex<<<dim3(NPIX, NB), 256>>>();

    k_final<<<dim3(7, NB), 256>>>(w_con2, b_con2, out);
}

// round 14
// speedup vs baseline: 1.1158x; 1.1158x over previous
#include <cuda_runtime.h>
#include <math.h>

#define NB    8
#define NC    64
#define NPIX  1600
#define TOPK  10
#define TKPAD 12
#define NNZ   (NPIX * TOPK)
#define SORTN 2048
#define FULLW 0xFFFFFFFFu

// ---------------- static scratch (no runtime allocation) ----------------
__device__ float g_xx  [NB * NPIX];
__device__ unsigned long long g_skey[NB * NPIX];   // sorted (val,idx) keys
__device__ unsigned short g_rs[NB * NPIX];         // run start per sorted pos
__device__ unsigned short g_re[NB * NPIX];         // run end per sorted pos
__device__ int   g_dvc [NB * NPIX];                // DV counters (global)
__device__ int   g_cur [NB * NPIX];                // CSR fill cursors
__device__ int   g_topk[NB * NPIX * TKPAD];
__device__ float g_dv2 [NB * NPIX];
__device__ int   g_off [NB * (NPIX + 1)];
__device__ int   g_ecol[NB * NNZ];
__device__ float g_Z   [NB * NPIX * NC];           // RAW X@W + b (dv2 applied in k_edge)
__device__ float g_Y   [NB * NPIX * NC];
__device__ float g_Hf  [NB * NPIX * NC];

__device__ __forceinline__ float4 f4add(float4 a, float4 b) {
    a.x += b.x; a.y += b.y; a.z += b.z; a.w += b.w; return a;
}
__device__ __forceinline__ float4 f4fma(float4 a, float4 z, float s) {
    a.x += z.x * s; a.y += z.y * s; a.z += z.z * s; a.w += z.w * s; return a;
}
__device__ __forceinline__ unsigned long long u64min_(unsigned long long a, unsigned long long b) { return a < b ? a : b; }
__device__ __forceinline__ unsigned long long u64max_(unsigned long long a, unsigned long long b) { return a > b ? a : b; }

// ---------------- K1: fused [layer-1 GEMM tiles | 1x1 conv + counter init]
__global__ void k_convgemm(const float* __restrict__ x,
                           const float* __restrict__ wc1,
                           const float* __restrict__ bc1,
                           const float* __restrict__ W,
                           const float* __restrict__ bias,
                           float* __restrict__ out)
{
    __shared__ float As[64 * 64];
    __shared__ float Ws[64 * 64];
    int t = threadIdx.x;

    if (blockIdx.x < 200) {
        int b  = blockIdx.x / 25;
        int r0 = (blockIdx.x - b * 25) * 64;
        const float* Xb = x + ((size_t)b * NPIX + r0) * NC;
        for (int i = t; i < 4096; i += 256) { As[i] = Xb[i]; Ws[i] = W[i]; }
        __syncthreads();
        int tx = t & 15, ty = t >> 4;
        int c4 = tx * 4, r4 = ty * 4;
        float acc[4][4];
        #pragma unroll
        for (int i = 0; i < 4; i++)
            #pragma unroll
            for (int j = 0; j < 4; j++) acc[i][j] = 0.f;
        for (int k = 0; k < 64; k += 4) {
            float4 w0 = *(const float4*)&Ws[(k+0)*64 + c4];
            float4 w1 = *(const float4*)&Ws[(k+1)*64 + c4];
            float4 w2 = *(const float4*)&Ws[(k+2)*64 + c4];
            float4 w3 = *(const float4*)&Ws[(k+3)*64 + c4];
            #pragma unroll
            for (int i = 0; i < 4; i++) {
                float4 a = *(const float4*)&As[(r4+i)*64 + k];
                acc[i][0] += a.x*w0.x + a.y*w1.x + a.z*w2.x + a.w*w3.x;
                acc[i][1] += a.x*w0.y + a.y*w1.y + a.z*w2.y + a.w*w3.y;
                acc[i][2] += a.x*w0.z + a.y*w1.z + a.z*w2.z + a.w*w3.z;
                acc[i][3] += a.x*w0.w + a.y*w1.w + a.z*w2.w + a.w*w3.w;
            }
        }
        float4 bv = *(const float4*)&bias[c4];
        #pragma unroll
        for (int i = 0; i < 4; i++) {
            int r = r0 + r4 + i;
            float4 o;
            o.x = acc[i][0] + bv.x;
            o.y = acc[i][1] + bv.y;
            o.z = acc[i][2] + bv.z;
            o.w = acc[i][3] + bv.w;
            *(float4*)&g_Z[((size_t)b*NPIX + r) * NC + c4] = o;   // raw
        }
    } else {
        int idx = blockIdx.x - 200;                 // 0..55
        int b = idx / 7;
        float* ws = As;
        if (t < NC) ws[t] = wc1[t];
        __syncthreads();
        int gid = idx * 256 + t;
        if (gid < NB * NPIX) { g_dvc[gid] = 0; g_cur[gid] = 0; }
        if (gid < NB) out[gid] = 0.f;
        int p = (idx - b * 7) * 256 + t;
        if (p >= NPIX) return;
        const float* xb = x + (size_t)b * NC * NPIX;
        float acc = bc1[0];
        #pragma unroll
        for (int c = 0; c < NC; c++) acc += xb[c*NPIX + p] * ws[c];
        g_xx[b*NPIX + p] = fmaxf(acc, 0.f);
    }
}

// ---------------- K2: softmax + sort + run bounds (8 blocks)
__global__ __launch_bounds__(1024) void k_sortA()
{
    int b = blockIdx.x, t = threadIdx.x;
    __shared__ unsigned long long skey[SORTN];
    __shared__ float rf[1024];

    float v0 = g_xx[b*NPIX + t];
    float v1 = (t + 1024 < NPIX) ? g_xx[b*NPIX + t + 1024] : -3.4e38f;
    rf[t] = fmaxf(v0, v1); __syncthreads();
    for (int s = 512; s > 0; s >>= 1) { if (t < s) rf[t] = fmaxf(rf[t], rf[t+s]); __syncthreads(); }
    float mx = rf[0]; __syncthreads();
    float e0 = expf(v0 - mx);
    float e1 = (t + 1024 < NPIX) ? expf(v1 - mx) : 0.f;
    rf[t] = e0 + e1; __syncthreads();
    for (int s = 512; s > 0; s >>= 1) { if (t < s) rf[t] += rf[t+s]; __syncthreads(); }
    float inv = 1.f / rf[0]; __syncthreads();

    unsigned long long a0 = ((unsigned long long)__float_as_uint(e0 * inv) << 32) | (unsigned)t;
    unsigned long long a1 = (t + 1024 < NPIX)
        ? (((unsigned long long)__float_as_uint(e1 * inv) << 32) | (unsigned)(t + 1024))
        : 0xFFFFFFFFFFFFFFFFull;

    #define REGPHASE(KSZ, J) { \
        unsigned long long p0 = __shfl_xor_sync(FULLW, a0, (J)); \
        unsigned long long p1 = __shfl_xor_sync(FULLW, a1, (J)); \
        int i0 = t, i1 = t + 1024; \
        bool m0 = (((i0 & (J)) == 0) == ((i0 & (KSZ)) == 0)); \
        bool m1 = (((i1 & (J)) == 0) == ((i1 & (KSZ)) == 0)); \
        a0 = m0 ? u64min_(a0, p0) : u64max_(a0, p0); \
        a1 = m1 ? u64min_(a1, p1) : u64max_(a1, p1); }

    for (int ksz = 2; ksz <= 32; ksz <<= 1)
        for (int j = ksz >> 1; j >= 1; j >>= 1)
            REGPHASE(ksz, j);
    skey[t] = a0; skey[t + 1024] = a1; __syncthreads();

    for (int ksz = 64; ksz <= SORTN; ksz <<= 1) {
        int jstart = ksz >> 1;
        if (ksz == SORTN) {
            unsigned long long lo = u64min_(a0, a1), hi = u64max_(a0, a1);
            a0 = lo; a1 = hi;
            skey[t] = a0; skey[t + 1024] = a1; __syncthreads();
            jstart = 512;
        }
        for (int j = jstart; j >= 32; j >>= 1) {
            #pragma unroll
            for (int r = 0; r < 2; r++) {
                int i = t + r * 1024;
                int ixj = i ^ j;
                if (ixj > i) {
                    unsigned long long a = skey[i], c = skey[ixj];
                    bool up = ((i & ksz) == 0);
                    if ((a > c) == up) { skey[i] = c; skey[ixj] = a; }
                }
            }
            __syncthreads();
        }
        a0 = skey[t]; a1 = skey[t + 1024];
        for (int j = 16; j >= 1; j >>= 1)
            REGPHASE(ksz, j);
        skey[t] = a0; skey[t + 1024] = a1; __syncthreads();
    }

    for (int p = t; p < NPIX; p += 1024) {
        unsigned v = (unsigned)(skey[p] >> 32);
        int lo = 0, hi = p;
        while (lo < hi) { int m = (lo + hi) >> 1;
            if ((unsigned)(skey[m] >> 32) < v) lo = m + 1; else hi = m; }
        int lo2 = p + 1, hi2 = NPIX;
        while (lo2 < hi2) { int m = (lo2 + hi2) >> 1;
            if ((unsigned)(skey[m] >> 32) <= v) lo2 = m + 1; else hi2 = m; }
        g_skey[b*NPIX + p] = skey[p];
        g_rs[b*NPIX + p] = (unsigned short)lo;
        g_re[b*NPIX + p] = (unsigned short)(lo2 - 1);
    }
}

// ---------------- K3: top-k walk, 8 slices per batch (64 blocks)
__global__ __launch_bounds__(256) void k_walk()
{
    int b = blockIdx.y, slice = blockIdx.x, t = threadIdx.x;
    __shared__ unsigned long long sk[NPIX];
    __shared__ unsigned short rs[NPIX], re[NPIX];
    for (int p = t; p < NPIX; p += 256) {
        sk[p] = g_skey[b*NPIX + p];
        rs[p] = g_rs[b*NPIX + p];
        re[p] = g_re[b*NPIX + p];
    }
    __syncthreads();
    if (t >= 200) return;
    int p = slice * 200 + t;
    int i = (int)(sk[p] & 0xFFFFFFFFu);
    float vi = __uint_as_float((unsigned)(sk[p] >> 32));

    int out[TOPK]; int cnt = 0;
    int a = rs[p], bnd = re[p];
    for (int q = a; q <= bnd && cnt < TOPK; q++)
        out[cnt++] = (int)(sk[q] & 0xFFFFFFFFu);
    int L = a - 1, R = bnd + 1;
    while (cnt < TOPK) {
        float dL = (L >= 0)   ? vi - __uint_as_float((unsigned)(sk[L] >> 32)) : 3.4e38f;
        float dR = (R < NPIX) ? __uint_as_float((unsigned)(sk[R] >> 32)) - vi : 3.4e38f;
        if (dL < dR) {
            int s2 = rs[L];
            for (int q = s2; q <= L && cnt < TOPK; q++)
                out[cnt++] = (int)(sk[q] & 0xFFFFFFFFu);
            L = s2 - 1;
        } else if (dR < dL) {
            int e2 = re[R];
            for (int q = R; q <= e2 && cnt < TOPK; q++)
                out[cnt++] = (int)(sk[q] & 0xFFFFFFFFu);
            R = e2 + 1;
        } else {
            int sL = rs[L], eR = re[R];
            int qa = sL, qb = R;
            while (cnt < TOPK && (qa <= L || qb <= eR)) {
                int ia = (qa <= L)  ? (int)(sk[qa] & 0xFFFFFFFFu) : 0x7FFFFFFF;
                int ib = (qb <= eR) ? (int)(sk[qb] & 0xFFFFFFFFu) : 0x7FFFFFFF;
                if (ia < ib) { out[cnt++] = ia; qa++; }
                else         { out[cnt++] = ib; qb++; }
            }
            L = sL - 1; R = eR + 1;
        }
    }
    bool has = false;
    #pragma unroll
    for (int j2 = 0; j2 < TOPK; j2++) has |= (out[j2] == i);
    if (!has) out[TOPK-1] = i;

    int base = (b*NPIX + i) * TKPAD;
    #pragma unroll
    for (int j2 = 0; j2 < TOPK; j2++) {
        g_topk[base + j2] = out[j2];
        atomicAdd(&g_dvc[b*NPIX + out[j2]], 1);
    }
}

// ---------------- K4: scan DV -> offsets; dv2 (8 blocks, shfl scan)
__global__ __launch_bounds__(1024) void k_scan()
{
    int b = blockIdx.x, t = threadIdx.x;
    int lane = t & 31, wid = t >> 5;
    __shared__ int part[32];
    int p0 = t * 2;
    int d0 = (p0 < NPIX) ? g_dvc[b*NPIX + p0] : 0;
    int d1 = (p0 + 1 < NPIX) ? g_dvc[b*NPIX + p0 + 1] : 0;
    int sv = d0 + d1;
    int incl = sv;
    #pragma unroll
    for (int d2 = 1; d2 < 32; d2 <<= 1) {
        int vv = __shfl_up_sync(FULLW, incl, d2);
        if (lane >= d2) incl += vv;
    }
    if (lane == 31) part[wid] = incl;
    __syncthreads();
    if (wid == 0) {
        int w = part[lane];
        #pragma unroll
        for (int d2 = 1; d2 < 32; d2 <<= 1) {
            int vv = __shfl_up_sync(FULLW, w, d2);
            if (lane >= d2) w += vv;
        }
        part[lane] = w;
    }
    __syncthreads();
    int total_incl = incl + (wid ? part[wid-1] : 0);
    if (p0 < NPIX) {
        int excl = total_incl - sv;
        g_off[b*(NPIX+1) + p0]     = excl;
        g_off[b*(NPIX+1) + p0 + 1] = excl + d0;
        g_dv2[b*NPIX + p0]     = rsqrtf((float)d0);
        g_dv2[b*NPIX + p0 + 1] = rsqrtf((float)d1);
    }
    if (t == 0) g_off[b*(NPIX+1) + NPIX] = NNZ;
}

// ---------------- K5: CSR fill, wide (global atomic cursors)
__global__ void k_fill()
{
    int b = blockIdx.y;
    int idx = blockIdx.x * 256 + threadIdx.x;
    if (idx >= NNZ) return;
    int e = idx / TOPK, j = idx - e * TOPK;
    int v = g_topk[(b*NPIX + e) * TKPAD + j];
    int ppos = atomicAdd(&g_cur[b*NPIX + v], 1);
    g_ecol[b*NNZ + g_off[b*(NPIX+1) + v] + ppos] = e;
}

// ---------------- hyperedge gather with fused 0.1*dv2 scaling per vertex term
__global__ void k_edge()
{
    int b = blockIdx.y, t = threadIdx.x;
    int e  = blockIdx.x * 16 + (t >> 4);
    int c4 = (t & 15) * 4;
    const int* __restrict__ tk = &g_topk[(b*NPIX + e) * TKPAD];
    int4 i0 = *(const int4*)tk;
    int4 i1 = *(const int4*)(tk + 4);
    int2 i2 = *(const int2*)(tk + 8);
    const float* __restrict__ dvb = &g_dv2[b*NPIX];
    float4 acc = make_float4(0.f, 0.f, 0.f, 0.f);
    #define EDGET(V) { int v_ = (V); float s_ = 0.1f * dvb[v_]; \
        acc = f4fma(acc, *(const float4*)&g_Z[((b*NPIX + v_) << 6) + c4], s_); }
    EDGET(i0.x); EDGET(i0.y); EDGET(i0.z); EDGET(i0.w);
    EDGET(i1.x); EDGET(i1.y); EDGET(i1.z); EDGET(i1.w);
    EDGET(i2.x); EDGET(i2.y);
    #undef EDGET
    *(float4*)&g_Y[((b*NPIX + e) << 6) + c4] = acc;
}

// ---------------- layer-2 GEMM: Z = Hf@W + b (raw; dv2 applied in k_edge)
__global__ void k_gemm2(const float* __restrict__ W,
                        const float* __restrict__ bias)
{
    int b  = blockIdx.y;
    int r0 = blockIdx.x * 64;
    __shared__ float As[64 * 64];
    __shared__ float Ws[64 * 64];
    int t = threadIdx.x;
    const float* Xb = g_Hf + ((size_t)b * NPIX + r0) * NC;
    for (int i = t; i < 4096; i += 256) { As[i] = Xb[i]; Ws[i] = W[i]; }
    __syncthreads();

    int tx = t & 15, ty = t >> 4;
    int c4 = tx * 4, r4 = ty * 4;
    float acc[4][4];
    #pragma unroll
    for (int i = 0; i < 4; i++)
        #pragma unroll
        for (int j = 0; j < 4; j++) acc[i][j] = 0.f;

    for (int k = 0; k < 64; k += 4) {
        float4 w0 = *(const float4*)&Ws[(k+0)*64 + c4];
        float4 w1 = *(const float4*)&Ws[(k+1)*64 + c4];
        float4 w2 = *(const float4*)&Ws[(k+2)*64 + c4];
        float4 w3 = *(const float4*)&Ws[(k+3)*64 + c4];
        #pragma unroll
        for (int i = 0; i < 4; i++) {
            float4 a = *(const float4*)&As[(r4+i)*64 + k];
            acc[i][0] += a.x*w0.x + a.y*w1.x + a.z*w2.x + a.w*w3.x;
            acc[i][1] += a.x*w0.y + a.y*w1.y + a.z*w2.y + a.w*w3.y;
            acc[i][2] += a.x*w0.z + a.y*w1.z + a.z*w2.z + a.w*w3.z;
            acc[i][3] += a.x*w0.w + a.y*w1.w + a.z*w2.w + a.w*w3.w;
        }
    }
    float4 bv = *(const float4*)&bias[c4];
    #pragma unroll
    for (int i = 0; i < 4; i++) {
        int r = r0 + r4 + i;
        float4 o;
        o.x = acc[i][0] + bv.x;
        o.y = acc[i][1] + bv.y;
        o.z = acc[i][2] + bv.z;
        o.w = acc[i][3] + bv.w;
        *(float4*)&g_Z[((size_t)b*NPIX + r) * NC + c4] = o;
    }
}

// ---------------- vertex gather: block per vertex, 16 slices float4
__global__ void k_vertex()
{
    int b = blockIdx.y, u = blockIdx.x, t = threadIdx.x;
    int c4 = (t & 15) * 4, s = t >> 4;
    __shared__ float4 red[256];
    int o0 = g_off[b*(NPIX+1) + u];
    int o1 = g_off[b*(NPIX+1) + u + 1];
    float4 acc = make_float4(0.f, 0.f, 0.f, 0.f);
    for (int p = o0 + s; p < o1; p += 16) {
        int e = g_ecol[b*NNZ + p];
        acc = f4add(acc, *(const float4*)&g_Y[((b*NPIX + e) << 6) + c4]);
    }
    red[t] = acc; __syncthreads();
    if (t < 128) red[t] = f4add(red[t], red[t+128]); __syncthreads();
    if (t < 64)  red[t] = f4add(red[t], red[t+64]);  __syncthreads();
    if (t < 32)  red[t] = f4add(red[t], red[t+32]);  __syncthreads();
    if (t < 16) {
        float4 tot = f4add(red[t], red[t+16]);
        float sc = g_dv2[b*NPIX + u];
        float4 o;
        o.x = fmaxf(tot.x * sc, 0.f);
        o.y = fmaxf(tot.y * sc, 0.f);
        o.z = fmaxf(tot.z * sc, 0.f);
        o.w = fmaxf(tot.w * sc, 0.f);
        *(float4*)&g_Hf[((b*NPIX + u) << 6) + t*4] = o;
    }
}

// ---------------- final 1x1 conv + relu + per-batch sum
__global__ void k_final(const float* __restrict__ wc,
                        const float* __restrict__ bc,
                        float* __restrict__ out)
{
    int b = blockIdx.y, t = threadIdx.x;
    __shared__ float ws[NC];
    __shared__ float red[256];
    if (t < NC) ws[t] = wc[t];
    __syncthreads();
    const float* hb = g_Hf + (size_t)b * NPIX * NC;
    int p = blockIdx.x * 256 + t;
    float lsum = 0.f;
    if (p < NPIX) {
        float acc = bc[0];
        #pragma unroll
        for (int c = 0; c < NC; c++) acc += hb[c*NPIX + p] * ws[c];
        lsum = fmaxf(acc, 0.f);
    }
    red[t] = lsum; __syncthreads();
    for (int s = 128; s > 0; s >>= 1) { if (t < s) red[t] += red[t+s]; __syncthreads(); }
    if (t == 0) atomicAdd(&out[b], red[0]);
}

// ---------------- launch ----------------
extern "C" void kernel_launch(void* const* d_in, const int* in_sizes, int n_in,
                              void* d_out, int out_size)
{
    const float* x      = (const float*)d_in[0];
    const float* w_con1 = (const float*)d_in[1];
    const float* b_con1 = (const float*)d_in[2];
    const float* W1     = (const float*)d_in[3];
    const float* b1     = (const float*)d_in[4];
    const float* W2     = (const float*)d_in[5];
    const float* b2     = (const float*)d_in[6];
    const float* w_con2 = (const float*)d_in[7];
    const float* b_con2 = (const float*)d_in[8];
    float* out = (float*)d_out;

    k_convgemm<<<256, 256>>>(x, w_con1, b_con1, W1, b1, out);
    k_sortA<<<NB, 1024>>>();
    k_walk<<<dim3(8, NB), 256>>>();
    k_scan<<<NB, 1024>>>();
    k_fill<<<dim3(63, NB), 256>>>();

    // layer 1 (dv2 applied inside k_edge)
    k_edge<<<dim3(NPIX / 16, NB), 256>>>();
    k_vertex<<<dim3(NPIX, NB), 256>>>();

    // layer 2
    k_gemm2<<<dim3(NPIX / 64, NB), 256>>>(W2, b2);
    k_edge<<<dim3(NPIX / 16, NB), 256>>>();
    k_vertex<<<dim3(NPIX, NB), 256>>>();

    k_final<<<dim3(7, NB), 256>>>(w_con2, b_con2, out);
}